// round 9
// baseline (speedup 1.0000x reference)
#include <cuda_runtime.h>
#include <cuda_bf16.h>
#include <cuda_fp16.h>
#include <cstdint>

// Problem constants (AttentionPool: N=262144, D=512, H=128, B=1024)
#define MAXN 262144
#define MAXB 4096
#define DIM 512
#define HID 128

// ---------------------------------------------------------------------------
// Scratch (allocation-free rule: __device__ globals)
// ---------------------------------------------------------------------------
__device__ float g_scores[MAXN];
__device__ int   g_off[MAXB + 1];
// W1^T as fp16, layout [n][k]: n=0..127 rows, k=0..511 contiguous
__device__ __align__(16) unsigned short g_w1t[HID * DIM];
// x converted to fp16 by score kernel, row-major [N][D] (256 MB)
__device__ __align__(16) unsigned short g_xf16[(size_t)MAXN * DIM];

// ---------------------------------------------------------------------------
// Kernel 0 (fused prep): batch dtype detect (inline, per-thread broadcast
// load), segment offsets via binary search, W1^T fp16 transpose.
// ---------------------------------------------------------------------------
__global__ __launch_bounds__(256)
void prep_kernel(const void* __restrict__ batch, int n, int Bseg,
                 const float* __restrict__ W1)
{
    int idx = blockIdx.x * blockDim.x + threadIdx.x;

    // --- W1^T fp16: g_w1t[n*512 + k] = fp16(W1[k][n])
    if (idx < HID * DIM) {
        int nn = idx >> 9;         // 0..127
        int k  = idx & 511;        // 0..511
        float w = __ldg(W1 + (size_t)k * HID + nn);
        g_w1t[idx] = __half_as_ushort(__float2half_rn(w));
    }

    // --- segment offsets (dtype: int32 if last i32 word nonzero, else int64 LE)
    if (idx <= Bseg) {
        const int i32 = (__ldg((const int*)batch + (n - 1)) != 0);
        int lo = 0, hi = n;
        if (i32) {
            const int* a = (const int*)batch;
            while (lo < hi) { int m = (lo + hi) >> 1; if (__ldg(a + m) < idx) lo = m + 1; else hi = m; }
        } else {
            const long long* a = (const long long*)batch;
            while (lo < hi) { int m = (lo + hi) >> 1; if (__ldg(a + m) < (long long)idx) lo = m + 1; else hi = m; }
        }
        g_off[idx] = lo;
    }
}

// ---------------------------------------------------------------------------
// PTX helpers (all sm_80+ baseline -> safe for compute_103 target)
// ---------------------------------------------------------------------------
__device__ __forceinline__ void mma_f16(float* d, const uint32_t* a, const uint32_t* b)
{
    asm volatile(
        "mma.sync.aligned.m16n8k16.row.col.f32.f16.f16.f32 "
        "{%0,%1,%2,%3}, {%4,%5,%6,%7}, {%8,%9}, {%0,%1,%2,%3};"
        : "+f"(d[0]), "+f"(d[1]), "+f"(d[2]), "+f"(d[3])
        : "r"(a[0]), "r"(a[1]), "r"(a[2]), "r"(a[3]), "r"(b[0]), "r"(b[1]));
}
__device__ __forceinline__ void ldsm_x4(uint32_t* r, uint32_t addr)
{
    asm volatile("ldmatrix.sync.aligned.m8n8.x4.shared.b16 {%0,%1,%2,%3}, [%4];"
                 : "=r"(r[0]), "=r"(r[1]), "=r"(r[2]), "=r"(r[3]) : "r"(addr));
}
__device__ __forceinline__ void cp16(uint32_t dst, const void* src)
{
    asm volatile("cp.async.cg.shared.global [%0], [%1], 16;"
                 :: "r"(dst), "l"(src) : "memory");
}
__device__ __forceinline__ void cp_commit()
{
    asm volatile("cp.async.commit_group;" ::: "memory");
}
template <int N>
__device__ __forceinline__ void cp_wait()
{
    asm volatile("cp.async.wait_group %0;" :: "n"(N) : "memory");
}
__device__ __forceinline__ uint32_t smem_u32(const void* p)
{
    uint32_t a;
    asm("{ .reg .u64 t; cvta.to.shared.u64 t, %1; cvt.u32.u64 %0, t; }" : "=r"(a) : "l"(p));
    return a;
}

// ---------------------------------------------------------------------------
// Kernel 1: scores = tanh(x @ W1 + b1) @ W2 + b2  via single-pass fp16 mma.
// Side effect: writes x as fp16 to g_xf16 (consumed by pool kernel).
// Block: 128 rows x 128 cols (HID), 8 warps in 4x2 grid (warp tile 32x64).
// K loop: 8 tiles of 64. Rows padded to 144B -> conflict-free ldmatrix.
// B double-buffered via cp.async; A[t+1] LDGs issued BEFORE the B wait +
// barrier so DRAM latency is covered by barrier + compute phase.
// ---------------------------------------------------------------------------
#define KT       64
#define ROWPADB  144                      // bytes per smem row
#define TILE_B   (128 * ROWPADB)          // 18432 bytes per tile buffer
#define OFF_A    0
#define OFF_B0   (1 * TILE_B)
#define OFF_B1   (2 * TILE_B)
#define SMEM_REQ (3 * TILE_B)             // 55296 B

__global__ __launch_bounds__(256, 2)
void score_mma_kernel(const float* __restrict__ x,
                      const float* __restrict__ b1,
                      const float* __restrict__ W2,
                      const float* __restrict__ b2)
{
    extern __shared__ char bp[];
    const uint32_t sbase = smem_u32(bp);

    const int tid = threadIdx.x;
    const int wid = tid >> 5;
    const int lid = tid & 31;
    const int tig = lid & 3;             // 0..3
    const int warp_row = wid & 3;        // rows warp_row*32 ..
    const int warp_col = wid >> 2;       // cols warp_col*64 ..
    const int rowBase = blockIdx.x * 128;

    // ldmatrix per-lane addresses
    const uint32_t a_rl    = (uint32_t)(lid & 15);
    const uint32_t a_chalf = (uint32_t)((lid >> 4) * 16);
    uint32_t aA[2];
#pragma unroll
    for (int m = 0; m < 2; m++) {
        uint32_t row = (uint32_t)(warp_row * 32 + m * 16) + a_rl;
        aA[m] = sbase + OFF_A + row * ROWPADB + a_chalf;
    }
    const uint32_t b_lane = ((uint32_t)(lid & 7) + (uint32_t)((lid >> 4) & 1) * 8) * ROWPADB
                          + (uint32_t)((lid >> 3) & 1) * 16
                          + (uint32_t)warp_col * 64 * ROWPADB;

    float acc[2][8][4];
#pragma unroll
    for (int m = 0; m < 2; m++)
#pragma unroll
        for (int nt = 0; nt < 8; nt++)
#pragma unroll
            for (int j = 0; j < 4; j++) acc[m][nt][j] = 0.f;

    // --- prologue: B[0] via cp.async; A[0] LDGs into registers
    {
#pragma unroll
        for (int u = 0; u < 4; u++) {
            int idx = tid + u * 256;
            int nn = idx >> 3, c8 = idx & 7;
            uint32_t doff = (uint32_t)nn * ROWPADB + (uint32_t)c8 * 16;
            uint32_t goff = (uint32_t)nn * DIM + (uint32_t)c8 * 8;  // t=0
            cp16(sbase + OFF_B0 + doff, g_w1t + goff);
        }
        cp_commit();
    }
    float4 va[8];
#pragma unroll
    for (int u = 0; u < 4; u++) {
        int idx = tid + u * 256;
        int r = idx >> 3, c8 = idx & 7;
        const float4* src = reinterpret_cast<const float4*>(
            x + (size_t)(rowBase + r) * DIM + c8 * 8);
        va[2 * u]     = __ldg(src);
        va[2 * u + 1] = __ldg(src + 1);
    }

    for (int t = 0; t < 8; t++) {
        if (t > 0) __syncthreads();      // prior tile reads done before overwrite

        // --- convert prefetched A (fp32 -> fp16): store to smem + gmem side copy
#pragma unroll
        for (int u = 0; u < 4; u++) {
            int idx = tid + u * 256;
            int r = idx >> 3, c8 = idx & 7;
            float f[8] = {va[2 * u].x, va[2 * u].y, va[2 * u].z, va[2 * u].w,
                          va[2 * u + 1].x, va[2 * u + 1].y, va[2 * u + 1].z, va[2 * u + 1].w};
            uint32_t hp[4];
#pragma unroll
            for (int j = 0; j < 4; j++) {
                __half h0 = __float2half_rn(f[2 * j]);
                __half h1 = __float2half_rn(f[2 * j + 1]);
                hp[j] = (uint32_t)__half_as_ushort(h0) | ((uint32_t)__half_as_ushort(h1) << 16);
            }
            uint32_t off = (uint32_t)r * ROWPADB + (uint32_t)c8 * 16;
            uint4 v = make_uint4(hp[0], hp[1], hp[2], hp[3]);
            *(uint4*)(bp + OFF_A + off) = v;
            // side copy: x fp16 for pool kernel ([row][k] row-major)
            *reinterpret_cast<uint4*>(g_xf16 +
                (size_t)(rowBase + r) * DIM + t * KT + c8 * 8) = v;
        }

        // --- issue A[t+1] LDGs NOW (latency covered by wait + barrier + compute)
        if (t < 7) {
#pragma unroll
            for (int u = 0; u < 4; u++) {
                int idx = tid + u * 256;
                int r = idx >> 3, c8 = idx & 7;
                const float4* src = reinterpret_cast<const float4*>(
                    x + (size_t)(rowBase + r) * DIM + (t + 1) * KT + c8 * 8);
                va[2 * u]     = __ldg(src);
                va[2 * u + 1] = __ldg(src + 1);
            }
        }

        // --- issue B[t+1] cp.async into alternate buffer, wait for B[t]
        if (t < 7) {
            uint32_t bufo = ((t + 1) & 1) ? OFF_B1 : OFF_B0;
#pragma unroll
            for (int u = 0; u < 4; u++) {
                int idx = tid + u * 256;
                int nn = idx >> 3, c8 = idx & 7;
                uint32_t doff = (uint32_t)nn * ROWPADB + (uint32_t)c8 * 16;
                uint32_t goff = (uint32_t)nn * DIM + (uint32_t)(t + 1) * KT + (uint32_t)c8 * 8;
                cp16(sbase + bufo + doff, g_w1t + goff);
            }
            cp_commit();
            cp_wait<1>();                 // B[t] complete; B[t+1] may stay in flight
        } else {
            cp_wait<0>();
        }
        __syncthreads();

        // --- compute: 4 k-steps of 16, single pass
        const uint32_t bA = sbase + ((t & 1) ? OFF_B1 : OFF_B0) + b_lane;
#pragma unroll
        for (int ks = 0; ks < 4; ks++) {
            const uint32_t ko = (uint32_t)ks * 32;
            uint32_t a[2][4];
#pragma unroll
            for (int m = 0; m < 2; m++) ldsm_x4(a[m], aA[m] + ko);
#pragma unroll
            for (int ntp = 0; ntp < 4; ntp++) {
                const uint32_t no = (uint32_t)ntp * 16 * ROWPADB + ko;
                uint32_t bh[4];
                ldsm_x4(bh, bA + no);
#pragma unroll
                for (int m = 0; m < 2; m++) {
                    mma_f16(acc[m][2 * ntp],     a[m], bh);
                    mma_f16(acc[m][2 * ntp + 1], a[m], bh + 2);
                }
            }
        }
    }

    // --- epilogue: s = sum_col tanh(h + b1[col]) * W2[col], register-resident
    const int grp = lid >> 2;
    float p[2][2] = {{0.f, 0.f}, {0.f, 0.f}};
#pragma unroll
    for (int nt = 0; nt < 8; nt++) {
        int c0 = warp_col * 64 + nt * 8 + tig * 2;
        float b1a = __ldg(b1 + c0),     b1b = __ldg(b1 + c0 + 1);
        float w2a = __ldg(W2 + c0),     w2b = __ldg(W2 + c0 + 1);
#pragma unroll
        for (int m = 0; m < 2; m++) {
            p[m][0] += tanhf(acc[m][nt][0] + b1a) * w2a + tanhf(acc[m][nt][1] + b1b) * w2b;
            p[m][1] += tanhf(acc[m][nt][2] + b1a) * w2a + tanhf(acc[m][nt][3] + b1b) * w2b;
        }
    }
#pragma unroll
    for (int m = 0; m < 2; m++)
#pragma unroll
        for (int r = 0; r < 2; r++) {
            p[m][r] += __shfl_xor_sync(0xFFFFFFFF, p[m][r], 1);
            p[m][r] += __shfl_xor_sync(0xFFFFFFFF, p[m][r], 2);
        }

    __syncthreads();                     // tiles no longer needed; reuse smem
    float* red = (float*)bp;             // [128][2]
    if (tig == 0) {
#pragma unroll
        for (int m = 0; m < 2; m++)
#pragma unroll
            for (int r = 0; r < 2; r++) {
                int row = warp_row * 32 + m * 16 + r * 8 + grp;
                red[row * 2 + warp_col] = p[m][r];
            }
    }
    __syncthreads();
    if (tid < 128)
        g_scores[rowBase + tid] = red[tid * 2] + red[tid * 2 + 1] + __ldg(b2);
}

// ---------------------------------------------------------------------------
// Kernel 2 (fused softmax + pool): per-segment softmax over g_scores, then
// out[b, :] = sum_i w_i * x_f16[i, :].  Weights recomputed (exp) on the fly.
// (Per-segment max-shift == reference's global max-shift: shift-invariant;
//  the +1e-8 denom term contributes ~1e-9 relative.)
// 256 threads = 4 row-quarters (q) x 64 column-chunks (t, 8 halfs = 16B).
// ---------------------------------------------------------------------------
__global__ __launch_bounds__(256)
void pool_softmax_kernel(float* __restrict__ out)
{
    const int b = blockIdx.x;
    const int tid = threadIdx.x;
    const int q = tid >> 6;              // 0..3 row quarter
    const int t = tid & 63;              // column chunk
    __shared__ float red[256];
    __shared__ float sh[3][64][8];       // partials from quarters 1..3

    const int lo = g_off[b];
    const int hi = g_off[b + 1];

    // --- segment max
    float m = -3.402823466e38f;
    for (int i = lo + tid; i < hi; i += 256) m = fmaxf(m, g_scores[i]);
    red[tid] = m;
    __syncthreads();
    for (int s = 128; s > 0; s >>= 1) {
        if (tid < s) red[tid] = fmaxf(red[tid], red[tid + s]);
        __syncthreads();
    }
    const float mm = red[0];
    __syncthreads();

    // --- sum of exp
    float sum = 0.f;
    for (int i = lo + tid; i < hi; i += 256) sum += expf(g_scores[i] - mm);
    red[tid] = sum;
    __syncthreads();
    for (int s = 128; s > 0; s >>= 1) {
        if (tid < s) red[tid] += red[tid + s];
        __syncthreads();
    }
    const float inv = 1.f / (red[0] + 1e-8f);

    // --- weighted sum over this quarter's rows
    const int len = hi - lo;
    const int s0 = lo + (int)(((long long)len * q) >> 2);
    const int e0 = lo + (int)(((long long)len * (q + 1)) >> 2);

    const uint4* xv = reinterpret_cast<const uint4*>(g_xf16) + t;  // + i*64 per row
    float a[8];
#pragma unroll
    for (int j = 0; j < 8; j++) a[j] = 0.f;

    int i = s0;
    for (; i + 2 <= e0; i += 2) {
        float w0 = expf(__ldg(g_scores + i)     - mm) * inv;
        float w1 = expf(__ldg(g_scores + i + 1) - mm) * inv;
        uint4 v0 = __ldg(xv + (size_t)i * (DIM / 8));
        uint4 v1 = __ldg(xv + (size_t)(i + 1) * (DIM / 8));
        const uint32_t* u0 = &v0.x;
        const uint32_t* u1 = &v1.x;
#pragma unroll
        for (int j = 0; j < 4; j++) {
            float2 f0 = __half22float2(*reinterpret_cast<const __half2*>(&u0[j]));
            float2 f1 = __half22float2(*reinterpret_cast<const __half2*>(&u1[j]));
            a[2 * j]     += w0 * f0.x + w1 * f1.x;
            a[2 * j + 1] += w0 * f0.y + w1 * f1.y;
        }
    }
    for (; i < e0; i++) {
        float w = expf(__ldg(g_scores + i) - mm) * inv;
        uint4 v = __ldg(xv + (size_t)i * (DIM / 8));
        const uint32_t* u = &v.x;
#pragma unroll
        for (int j = 0; j < 4; j++) {
            float2 f = __half22float2(*reinterpret_cast<const __half2*>(&u[j]));
            a[2 * j]     += w * f.x;
            a[2 * j + 1] += w * f.y;
        }
    }

    if (q > 0) {
#pragma unroll
        for (int j = 0; j < 8; j++) sh[q - 1][t][j] = a[j];
    }
    __syncthreads();
    if (q == 0) {
#pragma unroll
        for (int j = 0; j < 8; j++)
            a[j] += sh[0][t][j] + sh[1][t][j] + sh[2][t][j];
        float4* o = reinterpret_cast<float4*>(out + (size_t)b * DIM + t * 8);
        o[0] = make_float4(a[0], a[1], a[2], a[3]);
        o[1] = make_float4(a[4], a[5], a[6], a[7]);
    }
}

// ---------------------------------------------------------------------------
extern "C" void kernel_launch(void* const* d_in, const int* in_sizes, int n_in,
                              void* d_out, int out_size)
{
    const float* x     = (const float*)d_in[0];
    const void*  batch = (const void*)d_in[1];
    const float* W1    = (const float*)d_in[2];
    const float* b1    = (const float*)d_in[3];
    const float* W2    = (const float*)d_in[4];
    const float* b2    = (const float*)d_in[5];
    float*       out   = (float*)d_out;

    const int n = in_sizes[1];
    const int Bseg = out_size / DIM;

    cudaFuncSetAttribute(score_mma_kernel,
                         cudaFuncAttributeMaxDynamicSharedMemorySize, SMEM_REQ);

    prep_kernel<<<(HID * DIM + 255) / 256, 256>>>(batch, n, Bseg, W1);
    score_mma_kernel<<<n / 128, 256, SMEM_REQ>>>(x, b1, W2, b2);
    pool_softmax_kernel<<<Bseg, 256>>>(out);
}

// round 10
// speedup vs baseline: 1.0242x; 1.0242x over previous
#include <cuda_runtime.h>
#include <cuda_bf16.h>
#include <cuda_fp16.h>
#include <cstdint>

// Problem constants (AttentionPool: N=262144, D=512, H=128, B=1024)
#define MAXN 262144
#define MAXB 4096
#define DIM 512
#define HID 128

// ---------------------------------------------------------------------------
// Scratch (allocation-free rule: __device__ globals)
// ---------------------------------------------------------------------------
__device__ float g_scores[MAXN];
__device__ int   g_off[MAXB + 1];
// W1^T as fp16, layout [n][k]: n=0..127 rows, k=0..511 contiguous
__device__ __align__(16) unsigned short g_w1t[HID * DIM];
// x converted to fp16 by score kernel, row-major [N][D] (256 MB)
__device__ __align__(16) unsigned short g_xf16[(size_t)MAXN * DIM];

// ---------------------------------------------------------------------------
// Kernel 0 (fused prep):
//  blocks 0..3   : W1^T fp16 transpose via smem (coalesced both sides)
//  blocks 4..259 : segment offsets via boundary scatter over sorted batch
// ---------------------------------------------------------------------------
#define TPAD 132   // halfs per smem tile row

__global__ __launch_bounds__(256)
void prep_kernel(const void* __restrict__ batch, int n, int Bseg,
                 const float* __restrict__ W1)
{
    __shared__ unsigned short tile[128][TPAD];
    const int tid = threadIdx.x;

    if (blockIdx.x < 4) {
        // --- W1 transpose: k-range [k0, k0+128) x all 128 n
        const int k0 = blockIdx.x * 128;
        // load 128 (k) x 32 (float4 over n) chunks, convert, scatter to tile
#pragma unroll
        for (int u = 0; u < 16; u++) {
            int idx = tid + u * 256;          // 4096 chunks
            int kr = idx >> 5;                // 0..127
            int c4 = idx & 31;                // float4 index over n
            float4 v = __ldg(reinterpret_cast<const float4*>(
                W1 + (size_t)(k0 + kr) * HID + c4 * 4));
            tile[c4 * 4 + 0][kr] = __half_as_ushort(__float2half_rn(v.x));
            tile[c4 * 4 + 1][kr] = __half_as_ushort(__float2half_rn(v.y));
            tile[c4 * 4 + 2][kr] = __half_as_ushort(__float2half_rn(v.z));
            tile[c4 * 4 + 3][kr] = __half_as_ushort(__float2half_rn(v.w));
        }
        __syncthreads();
        // write out coalesced: 128 (n) x 16 (uint4 over k) chunks
#pragma unroll
        for (int u = 0; u < 8; u++) {
            int idx = tid + u * 256;          // 2048 chunks
            int nn = idx >> 4;                // 0..127
            int c8 = idx & 15;                // uint4 over local k
            unsigned short h[8];
#pragma unroll
            for (int j = 0; j < 8; j++) h[j] = tile[nn][c8 * 8 + j];
            *reinterpret_cast<uint4*>(g_w1t + (size_t)nn * DIM + k0 + c8 * 8) =
                *reinterpret_cast<const uint4*>(h);
        }
        return;
    }

    // --- segment offsets by boundary scatter (no dependent-load chains)
    const int gid = (blockIdx.x - 4) * 256 + tid;     // 65536 threads
    const int i32 = (__ldg((const int*)batch + (n - 1)) != 0);
    for (int i = gid; i < n; i += 65536) {
        long long bi, bp;
        if (i32) {
            const int* a = (const int*)batch;
            bi = __ldg(a + i);
            bp = (i == 0) ? -1 : __ldg(a + i - 1);
        } else {
            const long long* a = (const long long*)batch;
            bi = __ldg(a + i);
            bp = (i == 0) ? -1 : __ldg(a + i - 1);
        }
        for (long long b = bp + 1; b <= bi; b++) g_off[b] = i;
        if (i == n - 1)
            for (long long b = bi + 1; b <= Bseg; b++) g_off[b] = n;
    }
}

// ---------------------------------------------------------------------------
// PTX helpers (all sm_80+ baseline -> safe for compute_103 target)
// ---------------------------------------------------------------------------
__device__ __forceinline__ void mma_f16(float* d, const uint32_t* a, const uint32_t* b)
{
    asm volatile(
        "mma.sync.aligned.m16n8k16.row.col.f32.f16.f16.f32 "
        "{%0,%1,%2,%3}, {%4,%5,%6,%7}, {%8,%9}, {%0,%1,%2,%3};"
        : "+f"(d[0]), "+f"(d[1]), "+f"(d[2]), "+f"(d[3])
        : "r"(a[0]), "r"(a[1]), "r"(a[2]), "r"(a[3]), "r"(b[0]), "r"(b[1]));
}
__device__ __forceinline__ void ldsm_x4(uint32_t* r, uint32_t addr)
{
    asm volatile("ldmatrix.sync.aligned.m8n8.x4.shared.b16 {%0,%1,%2,%3}, [%4];"
                 : "=r"(r[0]), "=r"(r[1]), "=r"(r[2]), "=r"(r[3]) : "r"(addr));
}
__device__ __forceinline__ void cp16(uint32_t dst, const void* src)
{
    asm volatile("cp.async.cg.shared.global [%0], [%1], 16;"
                 :: "r"(dst), "l"(src) : "memory");
}
__device__ __forceinline__ void cp_commit()
{
    asm volatile("cp.async.commit_group;" ::: "memory");
}
template <int N>
__device__ __forceinline__ void cp_wait()
{
    asm volatile("cp.async.wait_group %0;" :: "n"(N) : "memory");
}
__device__ __forceinline__ uint32_t smem_u32(const void* p)
{
    uint32_t a;
    asm("{ .reg .u64 t; cvta.to.shared.u64 t, %1; cvt.u32.u64 %0, t; }" : "=r"(a) : "l"(p));
    return a;
}

// ---------------------------------------------------------------------------
// Kernel 1: scores = tanh(x @ W1 + b1) @ W2 + b2  via single-pass fp16 mma.
// Side effect: writes x as fp16 to g_xf16 (consumed by pool kernel).
// Block: 128 rows x 128 cols (HID), 8 warps in 4x2 grid (warp tile 32x64).
// K loop: 8 tiles of 64. Rows padded to 144B -> conflict-free ldmatrix.
// (R8-measured arrangement: B cp.async double buffer; A prefetch LDGs after
//  the barrier, before compute.)
// ---------------------------------------------------------------------------
#define KT       64
#define ROWPADB  144                      // bytes per smem row
#define TILE_B   (128 * ROWPADB)          // 18432 bytes per tile buffer
#define OFF_A    0
#define OFF_B0   (1 * TILE_B)
#define OFF_B1   (2 * TILE_B)
#define SMEM_REQ (3 * TILE_B)             // 55296 B

__global__ __launch_bounds__(256, 2)
void score_mma_kernel(const float* __restrict__ x,
                      const float* __restrict__ b1,
                      const float* __restrict__ W2,
                      const float* __restrict__ b2)
{
    extern __shared__ char bp[];
    const uint32_t sbase = smem_u32(bp);

    const int tid = threadIdx.x;
    const int wid = tid >> 5;
    const int lid = tid & 31;
    const int tig = lid & 3;             // 0..3
    const int warp_row = wid & 3;        // rows warp_row*32 ..
    const int warp_col = wid >> 2;       // cols warp_col*64 ..
    const int rowBase = blockIdx.x * 128;

    // ldmatrix per-lane addresses
    const uint32_t a_rl    = (uint32_t)(lid & 15);
    const uint32_t a_chalf = (uint32_t)((lid >> 4) * 16);
    uint32_t aA[2];
#pragma unroll
    for (int m = 0; m < 2; m++) {
        uint32_t row = (uint32_t)(warp_row * 32 + m * 16) + a_rl;
        aA[m] = sbase + OFF_A + row * ROWPADB + a_chalf;
    }
    const uint32_t b_lane = ((uint32_t)(lid & 7) + (uint32_t)((lid >> 4) & 1) * 8) * ROWPADB
                          + (uint32_t)((lid >> 3) & 1) * 16
                          + (uint32_t)warp_col * 64 * ROWPADB;

    float acc[2][8][4];
#pragma unroll
    for (int m = 0; m < 2; m++)
#pragma unroll
        for (int nt = 0; nt < 8; nt++)
#pragma unroll
            for (int j = 0; j < 4; j++) acc[m][nt][j] = 0.f;

    // --- prologue: B[0] via cp.async; A[0] LDGs into registers
    {
#pragma unroll
        for (int u = 0; u < 4; u++) {
            int idx = tid + u * 256;
            int nn = idx >> 3, c8 = idx & 7;
            uint32_t doff = (uint32_t)nn * ROWPADB + (uint32_t)c8 * 16;
            uint32_t goff = (uint32_t)nn * DIM + (uint32_t)c8 * 8;  // t=0
            cp16(sbase + OFF_B0 + doff, g_w1t + goff);
        }
        cp_commit();
    }
    float4 va[8];
#pragma unroll
    for (int u = 0; u < 4; u++) {
        int idx = tid + u * 256;
        int r = idx >> 3, c8 = idx & 7;
        const float4* src = reinterpret_cast<const float4*>(
            x + (size_t)(rowBase + r) * DIM + c8 * 8);
        va[2 * u]     = __ldg(src);
        va[2 * u + 1] = __ldg(src + 1);
    }

    for (int t = 0; t < 8; t++) {
        if (t > 0) __syncthreads();      // prior tile reads done before overwrite

        // --- convert prefetched A (fp32 -> fp16): store to smem + gmem side copy
#pragma unroll
        for (int u = 0; u < 4; u++) {
            int idx = tid + u * 256;
            int r = idx >> 3, c8 = idx & 7;
            float f[8] = {va[2 * u].x, va[2 * u].y, va[2 * u].z, va[2 * u].w,
                          va[2 * u + 1].x, va[2 * u + 1].y, va[2 * u + 1].z, va[2 * u + 1].w};
            uint32_t hp[4];
#pragma unroll
            for (int j = 0; j < 4; j++) {
                __half h0 = __float2half_rn(f[2 * j]);
                __half h1 = __float2half_rn(f[2 * j + 1]);
                hp[j] = (uint32_t)__half_as_ushort(h0) | ((uint32_t)__half_as_ushort(h1) << 16);
            }
            uint32_t off = (uint32_t)r * ROWPADB + (uint32_t)c8 * 16;
            uint4 v = make_uint4(hp[0], hp[1], hp[2], hp[3]);
            *(uint4*)(bp + OFF_A + off) = v;
            // side copy: x fp16 for pool kernel ([row][k] row-major)
            *reinterpret_cast<uint4*>(g_xf16 +
                (size_t)(rowBase + r) * DIM + t * KT + c8 * 8) = v;
        }

        // --- issue B[t+1] cp.async into alternate buffer, wait for B[t]
        if (t < 7) {
            uint32_t bufo = ((t + 1) & 1) ? OFF_B1 : OFF_B0;
#pragma unroll
            for (int u = 0; u < 4; u++) {
                int idx = tid + u * 256;
                int nn = idx >> 3, c8 = idx & 7;
                uint32_t doff = (uint32_t)nn * ROWPADB + (uint32_t)c8 * 16;
                uint32_t goff = (uint32_t)nn * DIM + (uint32_t)(t + 1) * KT + (uint32_t)c8 * 8;
                cp16(sbase + bufo + doff, g_w1t + goff);
            }
            cp_commit();
            cp_wait<1>();                 // B[t] complete; B[t+1] may stay in flight
        } else {
            cp_wait<0>();
        }
        __syncthreads();

        // --- prefetch next A tile LDGs (latency hidden behind compute below)
        if (t < 7) {
#pragma unroll
            for (int u = 0; u < 4; u++) {
                int idx = tid + u * 256;
                int r = idx >> 3, c8 = idx & 7;
                const float4* src = reinterpret_cast<const float4*>(
                    x + (size_t)(rowBase + r) * DIM + (t + 1) * KT + c8 * 8);
                va[2 * u]     = __ldg(src);
                va[2 * u + 1] = __ldg(src + 1);
            }
        }

        // --- compute: 4 k-steps of 16, single pass
        const uint32_t bA = sbase + ((t & 1) ? OFF_B1 : OFF_B0) + b_lane;
#pragma unroll
        for (int ks = 0; ks < 4; ks++) {
            const uint32_t ko = (uint32_t)ks * 32;
            uint32_t a[2][4];
#pragma unroll
            for (int m = 0; m < 2; m++) ldsm_x4(a[m], aA[m] + ko);
#pragma unroll
            for (int ntp = 0; ntp < 4; ntp++) {
                const uint32_t no = (uint32_t)ntp * 16 * ROWPADB + ko;
                uint32_t bh[4];
                ldsm_x4(bh, bA + no);
#pragma unroll
                for (int m = 0; m < 2; m++) {
                    mma_f16(acc[m][2 * ntp],     a[m], bh);
                    mma_f16(acc[m][2 * ntp + 1], a[m], bh + 2);
                }
            }
        }
    }

    // --- epilogue: s = sum_col tanh(h + b1[col]) * W2[col], register-resident
    const int grp = lid >> 2;
    float p[2][2] = {{0.f, 0.f}, {0.f, 0.f}};
#pragma unroll
    for (int nt = 0; nt < 8; nt++) {
        int c0 = warp_col * 64 + nt * 8 + tig * 2;
        float b1a = __ldg(b1 + c0),     b1b = __ldg(b1 + c0 + 1);
        float w2a = __ldg(W2 + c0),     w2b = __ldg(W2 + c0 + 1);
#pragma unroll
        for (int m = 0; m < 2; m++) {
            p[m][0] += tanhf(acc[m][nt][0] + b1a) * w2a + tanhf(acc[m][nt][1] + b1b) * w2b;
            p[m][1] += tanhf(acc[m][nt][2] + b1a) * w2a + tanhf(acc[m][nt][3] + b1b) * w2b;
        }
    }
#pragma unroll
    for (int m = 0; m < 2; m++)
#pragma unroll
        for (int r = 0; r < 2; r++) {
            p[m][r] += __shfl_xor_sync(0xFFFFFFFF, p[m][r], 1);
            p[m][r] += __shfl_xor_sync(0xFFFFFFFF, p[m][r], 2);
        }

    __syncthreads();                     // tiles no longer needed; reuse smem
    float* red = (float*)bp;             // [128][2]
    if (tig == 0) {
#pragma unroll
        for (int m = 0; m < 2; m++)
#pragma unroll
            for (int r = 0; r < 2; r++) {
                int row = warp_row * 32 + m * 16 + r * 8 + grp;
                red[row * 2 + warp_col] = p[m][r];
            }
    }
    __syncthreads();
    if (tid < 128)
        g_scores[rowBase + tid] = red[tid * 2] + red[tid * 2 + 1] + __ldg(b2);
}

// ---------------------------------------------------------------------------
// Kernel 2 (fused softmax + pool): per-segment softmax over g_scores, then
// out[b, :] = sum_i w_i * x_f16[i, :].  Weights recomputed (exp) on the fly.
// (Per-segment max-shift == reference's global max-shift: shift-invariant;
//  the +1e-8 denom term contributes ~1e-9 relative.)
// 256 threads = 4 row-quarters (q) x 64 column-chunks (t, 8 halfs = 16B).
// ---------------------------------------------------------------------------
__global__ __launch_bounds__(256)
void pool_softmax_kernel(float* __restrict__ out)
{
    const int b = blockIdx.x;
    const int tid = threadIdx.x;
    const int q = tid >> 6;              // 0..3 row quarter
    const int t = tid & 63;              // column chunk
    __shared__ float red[256];
    __shared__ float sh[3][64][8];       // partials from quarters 1..3

    const int lo = g_off[b];
    const int hi = g_off[b + 1];

    // --- segment max
    float m = -3.402823466e38f;
    for (int i = lo + tid; i < hi; i += 256) m = fmaxf(m, g_scores[i]);
    red[tid] = m;
    __syncthreads();
    for (int s = 128; s > 0; s >>= 1) {
        if (tid < s) red[tid] = fmaxf(red[tid], red[tid + s]);
        __syncthreads();
    }
    const float mm = red[0];
    __syncthreads();

    // --- sum of exp
    float sum = 0.f;
    for (int i = lo + tid; i < hi; i += 256) sum += expf(g_scores[i] - mm);
    red[tid] = sum;
    __syncthreads();
    for (int s = 128; s > 0; s >>= 1) {
        if (tid < s) red[tid] += red[tid + s];
        __syncthreads();
    }
    const float inv = 1.f / (red[0] + 1e-8f);

    // --- weighted sum over this quarter's rows (unroll 4 for MLP)
    const int len = hi - lo;
    const int s0 = lo + (int)(((long long)len * q) >> 2);
    const int e0 = lo + (int)(((long long)len * (q + 1)) >> 2);

    const uint4* xv = reinterpret_cast<const uint4*>(g_xf16) + t;  // + i*64 per row
    float a[8];
#pragma unroll
    for (int j = 0; j < 8; j++) a[j] = 0.f;

    int i = s0;
    for (; i + 4 <= e0; i += 4) {
        float s0v = __ldg(g_scores + i);
        float s1v = __ldg(g_scores + i + 1);
        float s2v = __ldg(g_scores + i + 2);
        float s3v = __ldg(g_scores + i + 3);
        uint4 v0 = __ldg(xv + (size_t)(i + 0) * (DIM / 8));
        uint4 v1 = __ldg(xv + (size_t)(i + 1) * (DIM / 8));
        uint4 v2 = __ldg(xv + (size_t)(i + 2) * (DIM / 8));
        uint4 v3 = __ldg(xv + (size_t)(i + 3) * (DIM / 8));
        float w0 = expf(s0v - mm) * inv;
        float w1 = expf(s1v - mm) * inv;
        float w2 = expf(s2v - mm) * inv;
        float w3 = expf(s3v - mm) * inv;
        const uint32_t* u0 = &v0.x;
        const uint32_t* u1 = &v1.x;
        const uint32_t* u2 = &v2.x;
        const uint32_t* u3 = &v3.x;
#pragma unroll
        for (int j = 0; j < 4; j++) {
            float2 f0 = __half22float2(*reinterpret_cast<const __half2*>(&u0[j]));
            float2 f1 = __half22float2(*reinterpret_cast<const __half2*>(&u1[j]));
            float2 f2 = __half22float2(*reinterpret_cast<const __half2*>(&u2[j]));
            float2 f3 = __half22float2(*reinterpret_cast<const __half2*>(&u3[j]));
            a[2 * j]     += w0 * f0.x + w1 * f1.x + w2 * f2.x + w3 * f3.x;
            a[2 * j + 1] += w0 * f0.y + w1 * f1.y + w2 * f2.y + w3 * f3.y;
        }
    }
    for (; i < e0; i++) {
        float w = expf(__ldg(g_scores + i) - mm) * inv;
        uint4 v = __ldg(xv + (size_t)i * (DIM / 8));
        const uint32_t* u = &v.x;
#pragma unroll
        for (int j = 0; j < 4; j++) {
            float2 f = __half22float2(*reinterpret_cast<const __half2*>(&u[j]));
            a[2 * j]     += w * f.x;
            a[2 * j + 1] += w * f.y;
        }
    }

    if (q > 0) {
#pragma unroll
        for (int j = 0; j < 8; j++) sh[q - 1][t][j] = a[j];
    }
    __syncthreads();
    if (q == 0) {
#pragma unroll
        for (int j = 0; j < 8; j++)
            a[j] += sh[0][t][j] + sh[1][t][j] + sh[2][t][j];
        float4* o = reinterpret_cast<float4*>(out + (size_t)b * DIM + t * 8);
        o[0] = make_float4(a[0], a[1], a[2], a[3]);
        o[1] = make_float4(a[4], a[5], a[6], a[7]);
    }
}

// ---------------------------------------------------------------------------
extern "C" void kernel_launch(void* const* d_in, const int* in_sizes, int n_in,
                              void* d_out, int out_size)
{
    const float* x     = (const float*)d_in[0];
    const void*  batch = (const void*)d_in[1];
    const float* W1    = (const float*)d_in[2];
    const float* b1    = (const float*)d_in[3];
    const float* W2    = (const float*)d_in[4];
    const float* b2    = (const float*)d_in[5];
    float*       out   = (float*)d_out;

    const int n = in_sizes[1];
    const int Bseg = out_size / DIM;

    cudaFuncSetAttribute(score_mma_kernel,
                         cudaFuncAttributeMaxDynamicSharedMemorySize, SMEM_REQ);

    prep_kernel<<<4 + 256, 256>>>(batch, n, Bseg, W1);
    score_mma_kernel<<<n / 128, 256, SMEM_REQ>>>(x, b1, W2, b2);
    pool_softmax_kernel<<<Bseg, 256>>>(out);
}